// round 3
// baseline (speedup 1.0000x reference)
#include <cuda_runtime.h>
#include <cstdint>

#define NB 256   // batch
#define ND 16    // manifold dim
#define NH 128   // hidden
#define R2H 256  // 2H

// ---- scratch (device globals; no allocation) ----
__device__ float g_metric[NB * 256];                       // metric[b][i*16+j]
__device__ float g_PB[NB * 256];                           // points@rW1[0:16] + rb1
__device__ float g_M1[NB * ND * 256];                      // M1[b][i][o]
__device__ __align__(16) float g_M2T[NB * 256 * ND];       // M2T[b][o][j]
__device__ __align__(16) float g_rW1T[256 * ND];           // rW1T[o][k] = rW1[48+k][o]
__device__ float g_Spart[NB * ND * 256];                   // per-(b,i) partial sums

// single-MUFU tanh
__device__ __forceinline__ float tanh_fast(float x) {
    float y;
    asm("tanh.approx.f32 %0, %1;" : "=f"(y) : "f"(x));
    return y;
}

// packed f32x2 helpers
__device__ __forceinline__ uint64_t pk2(float lo, float hi) {
    uint64_t r; asm("mov.b64 %0, {%1, %2};" : "=l"(r) : "f"(lo), "f"(hi)); return r;
}
__device__ __forceinline__ uint64_t fma2(uint64_t a, uint64_t b, uint64_t c) {
    uint64_t d; asm("fma.rn.f32x2 %0, %1, %2, %3;" : "=l"(d) : "l"(a), "l"(b), "l"(c)); return d;
}
__device__ __forceinline__ void unpk2(uint64_t v, float& lo, float& hi) {
    asm("mov.b64 {%0, %1}, %2;" : "=f"(lo), "=f"(hi) : "l"(v));
}

// ============================================================================
// K_PRE: grid (NB, 4), 256 threads. Each y-block redundantly computes the
// metric MLP (cheap), then owns i in [4y, 4y+4) for M1 / M2T.
// y==0 additionally writes g_metric, g_PB; block (b==0,y==1) writes g_rW1T.
// ============================================================================
__global__ __launch_bounds__(256) void k_pre(
    const float* __restrict__ points,
    const float* __restrict__ mW1, const float* __restrict__ mb1,
    const float* __restrict__ mW2, const float* __restrict__ mb2,
    const float* __restrict__ rW1, const float* __restrict__ rb1)
{
    int b = blockIdx.x;
    int y = blockIdx.y;
    int t = threadIdx.x;
    __shared__ float pts[ND];
    __shared__ float mh[NH];
    __shared__ float mraw[256];
    __shared__ float met[256];

    if (t < ND) pts[t] = points[b * ND + t];
    __syncthreads();

    if (t < NH) {
        float a = mb1[t];
        #pragma unroll
        for (int p = 0; p < ND; p++) a = fmaf(pts[p], mW1[p * NH + t], a);
        mh[t] = fmaxf(a, 0.0f);
    }
    __syncthreads();

    {
        float a = mb2[t];
        #pragma unroll 8
        for (int h = 0; h < NH; h++) a = fmaf(mh[h], mW2[h * 256 + t], a);
        mraw[t] = a;
    }
    __syncthreads();

    {
        int i = t >> 4, j = t & 15;
        float m = 0.5f * (mraw[i * 16 + j] + mraw[j * 16 + i]) + (i == j ? 1e-6f : 0.0f);
        met[t] = m;
    }
    __syncthreads();

    if (y == 0) {
        g_metric[b * 256 + t] = met[t];
        float a = rb1[t];
        #pragma unroll
        for (int p = 0; p < ND; p++) a = fmaf(pts[p], rW1[p * 256 + t], a);
        g_PB[b * 256 + t] = a;
    }
    if (y == 1 && b == 0) {
        // transpose rW1 rows 48..63 -> rW1T[o][k]
        float4 v0, v1, v2, v3;
        v0.x = rW1[(48 + 0) * 256 + t];  v0.y = rW1[(48 + 1) * 256 + t];
        v0.z = rW1[(48 + 2) * 256 + t];  v0.w = rW1[(48 + 3) * 256 + t];
        v1.x = rW1[(48 + 4) * 256 + t];  v1.y = rW1[(48 + 5) * 256 + t];
        v1.z = rW1[(48 + 6) * 256 + t];  v1.w = rW1[(48 + 7) * 256 + t];
        v2.x = rW1[(48 + 8) * 256 + t];  v2.y = rW1[(48 + 9) * 256 + t];
        v2.z = rW1[(48 + 10) * 256 + t]; v2.w = rW1[(48 + 11) * 256 + t];
        v3.x = rW1[(48 + 12) * 256 + t]; v3.y = rW1[(48 + 13) * 256 + t];
        v3.z = rW1[(48 + 14) * 256 + t]; v3.w = rW1[(48 + 15) * 256 + t];
        float4* dst = (float4*)&g_rW1T[t * ND];
        dst[0] = v0; dst[1] = v1; dst[2] = v2; dst[3] = v3;
    }

    // per-thread column copies of rW1 rows 16..47
    float rwA[ND], rwB[ND];
    #pragma unroll
    for (int p = 0; p < ND; p++) {
        rwA[p] = rW1[(16 + p) * 256 + t];
        rwB[p] = rW1[(32 + p) * 256 + t];
    }

    float m2loc[4];
    #pragma unroll
    for (int ii = 0; ii < 4; ii++) {
        int i0 = y * 4 + ii;
        float a1 = 0.0f, a2 = 0.0f;
        #pragma unroll
        for (int p = 0; p < ND; p++) {
            float mv = met[i0 * 16 + p];
            a1 = fmaf(mv, rwA[p], a1);
            a2 = fmaf(mv, rwB[p], a2);
        }
        g_M1[(b * ND + i0) * 256 + t] = a1;
        m2loc[ii] = a2;
    }
    *(float4*)&g_M2T[(b * 256 + t) * ND + y * 4] =
        make_float4(m2loc[0], m2loc[1], m2loc[2], m2loc[3]);
}

// ============================================================================
// K2: main fused kernel. One block per (i, b); 256 threads.
//   Stage A: thread (j,k) computes christoffel[b,i,j,k]; packed-FMA MLP,
//            single-MUFU tanh, 3 LDS per 2-h iteration.
//   Stage B: thread o accumulates relu hidden sums over j (all f32x2).
// ============================================================================
__global__ __launch_bounds__(256) void k_main(
    const float* __restrict__ cW1, const float* __restrict__ cb1,
    const float* __restrict__ cW2, const float* __restrict__ cb2)
{
    int i = blockIdx.x;   // 0..15
    int b = blockIdx.y;   // 0..255
    int t = threadIdx.x;  // 0..255

    __shared__ float met[256];
    __shared__ __align__(16) float4 sAB[NH / 2];  // (w0a,w0b, w1a,w1b)
    __shared__ __align__(16) float4 sCD[NH / 2];  // (w2a,w2b, cba,cbb)
    __shared__ __align__(8)  float2 sV[NH / 2];   // (v2a,v2b)
    __shared__ __align__(16) float chs[256];

    met[t] = g_metric[b * 256 + t];
    if (t < NH / 2) {
        int q = t;
        sAB[q] = make_float4(cW1[2 * q], cW1[2 * q + 1],
                             cW1[NH + 2 * q], cW1[NH + 2 * q + 1]);
        sCD[q] = make_float4(cW1[2 * NH + 2 * q], cW1[2 * NH + 2 * q + 1],
                             cb1[2 * q], cb1[2 * q + 1]);
        sV[q]  = make_float2(cW2[2 * q], cW2[2 * q + 1]);
    }
    __syncthreads();

    // ---- Stage A ----
    {
        int j = t >> 4, k = t & 15;
        float mij = met[i * 16 + j];
        float mjk = met[j * 16 + k];
        float mki = met[i * 16 + k];   // metric symmetric
        uint64_t mij2 = pk2(mij, mij);
        uint64_t mjk2 = pk2(mjk, mjk);
        uint64_t mki2 = pk2(mki, mki);

        uint64_t acc2 = 0ull;  // packed (0.0f, 0.0f)
        #pragma unroll 8
        for (int q = 0; q < NH / 2; q++) {
            ulonglong2 ab = ((const ulonglong2*)sAB)[q];  // .x=w0 pair, .y=w1 pair
            ulonglong2 cd = ((const ulonglong2*)sCD)[q];  // .x=w2 pair, .y=cb pair
            uint64_t x = fma2(mij2, ab.x, cd.y);
            x = fma2(mjk2, ab.y, x);
            x = fma2(mki2, cd.x, x);
            float xa, xb; unpk2(x, xa, xb);
            uint64_t t2 = pk2(tanh_fast(xa), tanh_fast(xb));
            uint64_t v = ((const uint64_t*)sV)[q];
            acc2 = fma2(v, t2, acc2);
        }
        float lo, hi; unpk2(acc2, lo, hi);
        chs[t] = cb2[0] + lo + hi;
    }
    __syncthreads();

    // ---- Stage B ----
    {
        int o = t;
        // rw pairs, pre-packed layout: rW1T[o][k]
        const ulonglong2* rwp = (const ulonglong2*)&g_rW1T[o * ND];
        ulonglong2 rw0 = rwp[0], rw1 = rwp[1], rw2 = rwp[2], rw3 = rwp[3];

        const float4* m2p = (const float4*)&g_M2T[(b * 256 + o) * ND];
        float4 m2a = m2p[0], m2b = m2p[1], m2c = m2p[2], m2d = m2p[3];
        float m2[ND] = {m2a.x, m2a.y, m2a.z, m2a.w, m2b.x, m2b.y, m2b.z, m2b.w,
                        m2c.x, m2c.y, m2c.z, m2c.w, m2d.x, m2d.y, m2d.z, m2d.w};

        float pm = g_PB[b * 256 + o] + g_M1[(b * ND + i) * 256 + o];
        float s = 0.0f;
        #pragma unroll 4
        for (int j = 0; j < ND; j++) {
            const ulonglong2* chr = (const ulonglong2*)&chs[j * 16];
            uint64_t acc2 = 0ull;
            ulonglong2 c0 = chr[0], c1 = chr[1], c2 = chr[2], c3 = chr[3];
            acc2 = fma2(c0.x, rw0.x, acc2);
            acc2 = fma2(c0.y, rw0.y, acc2);
            acc2 = fma2(c1.x, rw1.x, acc2);
            acc2 = fma2(c1.y, rw1.y, acc2);
            acc2 = fma2(c2.x, rw2.x, acc2);
            acc2 = fma2(c2.y, rw2.y, acc2);
            acc2 = fma2(c3.x, rw3.x, acc2);
            acc2 = fma2(c3.y, rw3.y, acc2);
            float lo, hi; unpk2(acc2, lo, hi);
            float a = pm + m2[j] + lo + hi;
            s += fmaxf(a, 0.0f);
        }
        g_Spart[(b * ND + i) * 256 + o] = s;   // deterministic partials
    }
}

// ============================================================================
// K3: reduce partials, tiny output GEMM, symmetrize
// ============================================================================
__global__ __launch_bounds__(256) void k_final(
    const float* __restrict__ rW2, const float* __restrict__ rb2,
    float* __restrict__ out)
{
    int b = blockIdx.x;
    int t = threadIdx.x;
    __shared__ float Ss[256];
    __shared__ float raw[256];

    float s = 0.0f;
    #pragma unroll
    for (int i = 0; i < ND; i++) s += g_Spart[(b * ND + i) * 256 + t];
    Ss[t] = s * (1.0f / 256.0f);
    __syncthreads();

    float a = rb2[t];
    #pragma unroll 8
    for (int h = 0; h < R2H; h++) a = fmaf(Ss[h], rW2[h * 256 + t], a);
    raw[t] = a;
    __syncthreads();

    int i = t >> 4, j = t & 15;
    out[b * 256 + t] = 0.5f * (raw[i * 16 + j] + raw[j * 16 + i]);
}

// ============================================================================
extern "C" void kernel_launch(void* const* d_in, const int* in_sizes, int n_in,
                              void* d_out, int out_size)
{
    const float* points = (const float*)d_in[0];
    const float* mW1    = (const float*)d_in[1];
    const float* mb1    = (const float*)d_in[2];
    const float* mW2    = (const float*)d_in[3];
    const float* mb2    = (const float*)d_in[4];
    const float* cW1    = (const float*)d_in[5];
    const float* cb1    = (const float*)d_in[6];
    const float* cW2    = (const float*)d_in[7];
    const float* cb2    = (const float*)d_in[8];
    const float* rW1    = (const float*)d_in[9];
    const float* rb1    = (const float*)d_in[10];
    const float* rW2    = (const float*)d_in[11];
    const float* rb2    = (const float*)d_in[12];
    float* out = (float*)d_out;

    dim3 gpre(NB, 4);
    k_pre<<<gpre, 256>>>(points, mW1, mb1, mW2, mb2, rW1, rb1);
    dim3 grid2(ND, NB);
    k_main<<<grid2, 256>>>(cW1, cb1, cW2, cb2);
    k_final<<<NB, 256>>>(rW2, rb2, out);
}